// round 12
// baseline (speedup 1.0000x reference)
#include <cuda_runtime.h>
#include <cuda_fp16.h>
#include <math.h>
#include <stdint.h>

#define BATCH 512
#define LATENT 128

// ---------------- scratch (static device arrays; no runtime allocs) ----------
__device__ float    g_lp[BATCH * 32];
// pixel-major half2 buffers: [n][pix][ch-words]
__device__ uint32_t g_b0[BATCH * 64 * 64];
__device__ uint32_t g_b1[BATCH * 256 * 64];
__device__ uint32_t g_b2[BATCH * 1024 * 32];
// per-lane A-fragment weights: conv1/2 [cls][c][tap][mt][lane][4w], conv3 [c][cls][tap][lane][2w]
__device__ uint32_t g_wr1[4 * 8 * 4 * 8 * 32 * 4];   // 131072
__device__ uint32_t g_wr2[4 * 8 * 4 * 4 * 32 * 4];   // 65536
__device__ uint32_t g_wr3[4 * 4 * 4 * 32 * 2];       // 4096

// ---------------- helpers ----------------
__device__ __forceinline__ uint32_t packh2(float lo, float hi) {
    __half2 h = __floats2half2_rn(lo, hi);
    return *(uint32_t*)&h;
}
__device__ __forceinline__ void mma_f16(float* d, const uint32_t* a, const uint32_t* b) {
    asm("mma.sync.aligned.m16n8k16.row.col.f32.f16.f16.f32 "
        "{%0,%1,%2,%3}, {%4,%5,%6,%7}, {%8,%9}, {%0,%1,%2,%3};"
        : "+f"(d[0]), "+f"(d[1]), "+f"(d[2]), "+f"(d[3])
        : "r"(a[0]), "r"(a[1]), "r"(a[2]), "r"(a[3]), "r"(b[0]), "r"(b[1]));
}
__device__ __forceinline__ void ldsm4(uint32_t* d, uint32_t addr) {
    asm volatile("ldmatrix.sync.aligned.m8n8.x4.shared.b16 {%0,%1,%2,%3}, [%4];"
                 : "=r"(d[0]), "=r"(d[1]), "=r"(d[2]), "=r"(d[3]) : "r"(addr));
}
__device__ __forceinline__ uint32_t smaddr(const void* p) {
    return (uint32_t)__cvta_generic_to_shared(p);
}
__device__ __forceinline__ void cp16(uint32_t* dst, const void* src) {
    uint32_t s = smaddr(dst);
    asm volatile("cp.async.ca.shared.global [%0], [%1], 16;" :: "r"(s), "l"(src) : "memory");
}
__device__ __forceinline__ void cp_commit() {
    asm volatile("cp.async.commit_group;" ::: "memory");
}
template <int N>
__device__ __forceinline__ void cp_wait() {
    asm volatile("cp.async.wait_group %0;" :: "n"(N) : "memory");
}

// ---------------- stage 1: gating + soft-tree leaf probabilities -------------
__global__ void leaf_kernel(const float* __restrict__ x,
                            const float* __restrict__ gw,
                            const float* __restrict__ gb,
                            float* __restrict__ lp) {
    int b = blockIdx.x;
    int lane = threadIdx.x;
    __shared__ float xs[LATENT];
    __shared__ float gs[32];
    for (int k = lane; k < LATENT; k += 32) xs[k] = x[b * LATENT + k];
    __syncthreads();
    if (lane < 31) {
        float acc = gb[lane];
#pragma unroll 8
        for (int k = 0; k < LATENT; k++) acc += xs[k] * gw[k * 31 + lane];
        gs[lane] = 1.0f / (1.0f + expf(-acc));
    }
    __syncthreads();
    float dens = 1.0f;
    int l = lane;
#pragma unroll
    for (int d = 1; d <= 5; d++) {
        int par  = l >> (6 - d);
        int gate = (1 << (d - 1)) - 1 + par;
        int bit  = (l >> (5 - d)) & 1;
        float gv = gs[gate];
        dens *= bit ? (1.0f - gv) : gv;
    }
    lp[b * 32 + l] = dens;
}

// ---------------- stage 2: mix, 16-batch tile, pixel-major half2 words -------
__global__ void mix_kernel(const float* __restrict__ lp,
                           const float* __restrict__ z,
                           uint32_t* __restrict__ out0) {
    __shared__ float lps[16][32];
    int tid = threadIdx.x;
    int idx = blockIdx.x * 256 + tid;
    int b0 = blockIdx.y * 16;
    for (int i = tid; i < 512; i += 256)
        lps[i >> 5][i & 31] = lp[b0 * 32 + i];
    __syncthreads();
    int icp = idx & 63, pix = idx >> 6;
    const float4* z0 = (const float4*)(z + (size_t)(2 * icp * 64 + pix) * 32);
    const float4* z1 = (const float4*)(z + (size_t)((2 * icp + 1) * 64 + pix) * 32);
    float4 zr0[8], zr1[8];
#pragma unroll
    for (int j = 0; j < 8; j++) { zr0[j] = z0[j]; zr1[j] = z1[j]; }
#pragma unroll
    for (int bb = 0; bb < 16; bb++) {
        const float* lr = lps[bb];
        float a0 = 0.0f, a1 = 0.0f;
#pragma unroll
        for (int j = 0; j < 8; j++) {
            float4 u = zr0[j], v = zr1[j];
            a0 += u.x * lr[4 * j] + u.y * lr[4 * j + 1] + u.z * lr[4 * j + 2] + u.w * lr[4 * j + 3];
            a1 += v.x * lr[4 * j] + v.y * lr[4 * j + 1] + v.z * lr[4 * j + 2] + v.w * lr[4 * j + 3];
        }
        out0[(size_t)(b0 + bb) * 4096 + pix * 64 + icp] = packh2(a0, a1);
    }
}

// ---------------- merged weight prep: per-lane mma A-fragments ---------------
template <int COUT, int MSHIFT>
__device__ __forceinline__ void prep_frag(const float* __restrict__ w,
                                          uint32_t* __restrict__ wr, int idx) {
    constexpr int MT = 1 << MSHIFT;
    if (idx >= 4 * 8 * 4 * MT * 32 * 4) return;
    int j    = idx & 3;
    int lane = (idx >> 2) & 31;
    int mt   = (idx >> 7) & (MT - 1);
    int t    = (idx >> (7 + MSHIFT)) & 3;
    int c    = (idx >> (9 + MSHIFT)) & 7;
    int cls  = idx >> (12 + MSHIFT);
    int lg = lane >> 2, lt = lane & 3;
    int m  = mt * 16 + lg + 8 * (j & 1);
    int kk = lt + 4 * (j >> 1);
    int py = cls >> 1, px = cls & 1;
    int ra = t >> 1, rb = t & 1;
    int ky = 3 - py - 2 * ra;
    int kx = 3 - px - 2 * rb;
    int ch = 2 * (c * 8 + kk);
    float v0 = w[((size_t)ch * COUT + m) * 16 + ky * 4 + kx];
    float v1 = w[((size_t)(ch + 1) * COUT + m) * 16 + ky * 4 + kx];
    wr[idx] = packh2(v0, v1);
}

__global__ void prep_all(const float* __restrict__ w1, uint32_t* __restrict__ wr1,
                         const float* __restrict__ w2, uint32_t* __restrict__ wr2,
                         const float* __restrict__ w3, uint32_t* __restrict__ wr3) {
    int g = blockIdx.x;
    int tid = threadIdx.x;
    if (g < 512)      prep_frag<128, 3>(w1, wr1, g * 256 + tid);
    else if (g < 768) prep_frag<64, 2>(w2, wr2, (g - 512) * 256 + tid);
    else {
        int idx = (g - 768) * 256 + tid;
        if (idx >= 4096) return;
        int j    = idx & 1;
        int lane = (idx >> 1) & 31;
        int t    = (idx >> 6) & 3;
        int cls  = (idx >> 8) & 3;
        int c    = idx >> 10;
        int lg = lane >> 2, lt = lane & 3;
        int kk = lt + 4 * j;
        int oc = lg;
        int py = cls >> 1, px = cls & 1;
        int ra = t >> 1, rb = t & 1;
        int ky = 3 - py - 2 * ra;
        int kx = 3 - px - 2 * rb;
        int ch = 2 * (c * 8 + kk);
        float v0 = 0.0f, v1 = 0.0f;
        if (oc < 3) {
            v0 = w3[((size_t)ch * 3 + oc) * 16 + ky * 4 + kx];
            v1 = w3[((size_t)(ch + 1) * 3 + oc) * 16 + ky * 4 + kx];
        }
        wr3[idx] = packh2(v0, v1);
    }
}

// ---------------- conv1/conv2: fp16 mma, per-tap pipelined A LDG -------------
template <int CIN, int HIN, int COUT, int MGRP, int IMGB, bool RELU, int NBLK>
__launch_bounds__(256, NBLK)
__global__ void convt_h2(const uint32_t* __restrict__ in,
                         const uint32_t* __restrict__ wr,
                         const float* __restrict__ bias,
                         uint32_t* __restrict__ out) {
    constexpr int NPIX = HIN * HIN;
    constexpr int HOUT = 2 * HIN;
    constexpr int PW   = HIN + 2;
    constexpr int PPIX = PW * PW;
    constexpr int NGRP = 8 / MGRP;
    constexpr int NSUB = IMGB * NPIX / (8 * NGRP);
    constexpr int LOGH = (HIN == 8) ? 3 : 4;
    constexpr int MT   = COUT / 16;
    constexpr int ICPW = CIN / 2;
    constexpr int OCPW = COUT / 2;
    constexpr int NCH  = CIN / 16;
    constexpr int BSZ  = IMGB * PPIX * 12;

    extern __shared__ uint32_t smu[];
    uint32_t* Bbuf[2] = { smu, smu + BSZ };

    const int cls = blockIdx.x;
    const int img0 = blockIdx.y * IMGB;
    const int py = cls >> 1, px = cls & 1;
    const int tid = threadIdx.x;
    const int warp = tid >> 5, lane = tid & 31;
    const int lg = lane >> 2, lt = lane & 3;
    const int m0 = (warp % MGRP) * 32;
    const int n0 = (warp / MGRP) * (NSUB * 8);

    for (int i = tid; i < 2 * BSZ; i += 256) Bbuf[0][i] = 0;
    __syncthreads();

    int toffB[4];
#pragma unroll
    for (int t = 0; t < 4; t++)
        toffB[t] = ((py - 1 + (t >> 1)) * PW + (px - 1 + (t & 1))) * 48;

    uint32_t bslot[NSUB / 2];
#pragma unroll
    for (int j = 0; j < NSUB / 2; j++) {
        int s = 2 * j + (lane >> 4);
        int n = n0 + s * 8 + (lane & 7);
        int im = n >> (2 * LOGH);
        int pix = n & (NPIX - 1);
        int q = pix >> LOGH, r = pix & (HIN - 1);
        bslot[j] = (im * PPIX + (q + 1) * PW + (r + 1)) * 48 + ((lane >> 3) & 1) * 16;
    }

    float d[2][NSUB][4];
#pragma unroll
    for (int mm = 0; mm < 2; mm++)
#pragma unroll
        for (int s = 0; s < NSUB; s++)
#pragma unroll
            for (int j = 0; j < 4; j++) d[mm][s][j] = 0.0f;

    // A fragment base: [cls][c][tap][mt][lane][4]
    const uint32_t* wA = wr + ((size_t)cls * NCH * 4 * MT + (m0 >> 4)) * 128 + lane * 4;

    auto prefetchB = [&](int c) {
        uint32_t* B = Bbuf[c & 1];
        for (int idx = tid; idx < IMGB * NPIX * 2; idx += 256) {
            int part = idx & 1;
            int rest = idx >> 1;
            int pix = rest & (NPIX - 1);
            int im  = rest >> (2 * LOGH);
            int q = pix >> LOGH, r = pix & (HIN - 1);
            cp16(B + (im * PPIX + (q + 1) * PW + (r + 1)) * 12 + part * 4,
                 in + ((size_t)(img0 + im) * NPIX + pix) * ICPW + c * 8 + part * 4);
        }
    };

    prefetchB(0);
    cp_commit();

    for (int c = 0; c < NCH; c++) {
        const uint32_t* wAc = wA + (size_t)(c * 4) * MT * 128;
        // tap-0 A fragments issue before the wait (overlaps staging latency)
        uint4 a_cur[2], a_nxt[2];
        a_cur[0] = *(const uint4*)(wAc);
        a_cur[1] = *(const uint4*)(wAc + 128);

        if (c + 1 < NCH) { prefetchB(c + 1); cp_commit(); cp_wait<1>(); }
        else             { cp_wait<0>(); }
        __syncthreads();
        const uint32_t bb = smaddr(Bbuf[c & 1]);

#pragma unroll
        for (int t = 0; t < 4; t++) {
            if (t < 3) {
                const uint32_t* wAn = wAc + (size_t)(t + 1) * MT * 128;
                a_nxt[0] = *(const uint4*)(wAn);
                a_nxt[1] = *(const uint4*)(wAn + 128);
            }
            const int tb = toffB[t];
#pragma unroll
            for (int j = 0; j < NSUB / 2; j++) {
                uint32_t bf[4];
                ldsm4(bf, bb + bslot[j] + tb);
                mma_f16(d[0][2 * j],     (const uint32_t*)&a_cur[0], bf + 0);
                mma_f16(d[1][2 * j],     (const uint32_t*)&a_cur[1], bf + 0);
                mma_f16(d[0][2 * j + 1], (const uint32_t*)&a_cur[0], bf + 2);
                mma_f16(d[1][2 * j + 1], (const uint32_t*)&a_cur[1], bf + 2);
            }
            if (t < 3) { a_cur[0] = a_nxt[0]; a_cur[1] = a_nxt[1]; }
        }
        __syncthreads();
    }

    // epilogue: bias(+ReLU), shfl pair-exchange, pixel-major packed writes
    float bv[2][2];
#pragma unroll
    for (int mm = 0; mm < 2; mm++) {
        bv[mm][0] = bias[m0 + mm * 16 + lg];
        bv[mm][1] = bias[m0 + mm * 16 + lg + 8];
    }
#pragma unroll
    for (int mm = 0; mm < 2; mm++) {
#pragma unroll
        for (int s = 0; s < NSUB; s++) {
            int nb = n0 + s * 8 + 2 * lt;
            int im = nb >> (2 * LOGH);
            int pix = nb & (NPIX - 1);
            int q = pix >> LOGH, r = pix & (HIN - 1);
            int op0 = (2 * q + py) * HOUT + 2 * r + px;
            uint32_t* outw = out + (size_t)(img0 + im) * HOUT * HOUT * OCPW;
#pragma unroll
            for (int half = 0; half < 2; half++) {
                int oc = m0 + mm * 16 + lg + 8 * half;
                float v0 = d[mm][s][2 * half]     + bv[mm][half];
                float v1 = d[mm][s][2 * half + 1] + bv[mm][half];
                if (RELU) { v0 = fmaxf(v0, 0.0f); v1 = fmaxf(v1, 0.0f); }
                float p0 = __shfl_down_sync(0xffffffffu, v0, 4);
                float p1 = __shfl_down_sync(0xffffffffu, v1, 4);
                if (!(lg & 1)) {
                    int ocp = oc >> 1;
                    outw[(size_t)op0 * OCPW + ocp]       = packh2(v0, p0);
                    outw[(size_t)(op0 + 2) * OCPW + ocp] = packh2(v1, p1);
                }
            }
        }
    }
}

// ---------------- conv3: fused classes, swapped roles, weights by LDG --------
__launch_bounds__(256, 2)
__global__ void convt3_h2(const uint32_t* __restrict__ in,
                          const uint32_t* __restrict__ wr,
                          const float* __restrict__ bias,
                          float* __restrict__ out) {
    constexpr int HIN = 32, HOUT = 64;
    constexpr int PW = HIN + 2;
    constexpr int ROWS = 18;
    constexpr int PSUB = 4;
    constexpr int BSZ = ROWS * PW * 12;

    extern __shared__ uint32_t smu[];
    uint32_t* Bbuf[2] = { smu, smu + BSZ };

    const int q0 = blockIdx.x * 16;
    const int img = blockIdx.y;
    const int tid = threadIdx.x;
    const int warp = tid >> 5, lane = tid & 31;
    const int lg = lane >> 2, lt = lane & 3;

    for (int i = tid; i < 2 * BSZ; i += 256) Bbuf[0][i] = 0;
    __syncthreads();

    uint32_t aslot[PSUB];
#pragma unroll
    for (int s = 0; s < PSUB; s++) {
        int p = warp * 64 + s * 16;
        int ql = p >> 5, r0 = p & 31;
        aslot[s] = ((ql + 1) * PW + r0 + 1 + (lane & 7) + 8 * ((lane >> 3) & 1)) * 48
                 + (lane >> 4) * 16;
    }

    float d[4][PSUB][4];
#pragma unroll
    for (int c = 0; c < 4; c++)
#pragma unroll
        for (int s = 0; s < PSUB; s++)
#pragma unroll
            for (int j = 0; j < 4; j++) d[c][s][j] = 0.0f;

    auto prefetchB = [&](int c) {
        uint32_t* B = Bbuf[c & 1];
        for (int idx = tid; idx < ROWS * 32 * 2; idx += 256) {
            int part = idx & 1;
            int rest = idx >> 1;
            int col = rest & 31;
            int rr  = rest >> 5;
            int row = q0 - 1 + rr;
            if (row >= 0 && row < HIN)
                cp16(B + (rr * PW + col + 1) * 12 + part * 4,
                     in + ((size_t)img * 1024 + row * 32 + col) * 32 + c * 8 + part * 4);
        }
    };

    prefetchB(0);
    cp_commit();

    for (int c = 0; c < 4; c++) {
        if (c + 1 < 4) { prefetchB(c + 1); cp_commit(); cp_wait<1>(); }
        else           { cp_wait<0>(); }
        __syncthreads();
        const uint32_t bb = smaddr(Bbuf[c & 1]);

#pragma unroll
        for (int cls = 0; cls < 4; cls++) {
            const int py = cls >> 1, px = cls & 1;
            uint2 wv[4];
#pragma unroll
            for (int t = 0; t < 4; t++)
                wv[t] = *(const uint2*)(wr + (((c * 4 + cls) * 4 + t) * 32 + lane) * 2);
#pragma unroll
            for (int t = 0; t < 4; t++) {
                const int ra = t >> 1, rb = t & 1;
                const int sh = ((py - 1 + ra) * PW + (px - 1 + rb)) * 48;
                uint32_t b[2] = { wv[t].x, wv[t].y };
#pragma unroll
                for (int s = 0; s < PSUB; s++) {
                    uint32_t af[4];
                    ldsm4(af, bb + aslot[s] + sh);
                    mma_f16(d[cls][s], af, b);
                }
            }
        }
        __syncthreads();
    }

    float bias_s[3];
    bias_s[0] = bias[0]; bias_s[1] = bias[1]; bias_s[2] = bias[2];
    float* outb = out + (size_t)img * 3 * HOUT * HOUT;
    if (lt < 2) {
#pragma unroll
        for (int cls = 0; cls < 4; cls++) {
            const int py = cls >> 1, px = cls & 1;
#pragma unroll
            for (int s = 0; s < PSUB; s++) {
#pragma unroll
                for (int rowh = 0; rowh < 2; rowh++) {
                    int p = warp * 64 + s * 16 + lg + 8 * rowh;
                    int q = q0 + (p >> 5), r = p & 31;
                    int oy = 2 * q + py, ox = 2 * r + px;
#pragma unroll
                    for (int cc = 0; cc < 2; cc++) {
                        int oc = 2 * lt + cc;
                        if (oc < 3) {
                            float v = d[cls][s][2 * rowh + cc] + bias_s[oc];
                            outb[((size_t)oc * HOUT + oy) * HOUT + ox] = v;
                        }
                    }
                }
            }
        }
    }
}

// ---------------- launch -----------------------------------------------------
extern "C" void kernel_launch(void* const* d_in, const int* in_sizes, int n_in,
                              void* d_out, int out_size) {
    const float* x  = (const float*)d_in[0];
    const float* gw = (const float*)d_in[1];
    const float* gb = (const float*)d_in[2];
    const float* z  = (const float*)d_in[3];
    const float* w1 = (const float*)d_in[4];
    const float* b1 = (const float*)d_in[5];
    const float* w2 = (const float*)d_in[6];
    const float* b2 = (const float*)d_in[7];
    const float* w3 = (const float*)d_in[8];
    const float* b3 = (const float*)d_in[9];
    float* out = (float*)d_out;

    float *lp;
    uint32_t *bf0, *bf1, *bf2, *wr1, *wr2, *wr3;
    cudaGetSymbolAddress((void**)&lp,  g_lp);
    cudaGetSymbolAddress((void**)&bf0, g_b0);
    cudaGetSymbolAddress((void**)&bf1, g_b1);
    cudaGetSymbolAddress((void**)&bf2, g_b2);
    cudaGetSymbolAddress((void**)&wr1, g_wr1);
    cudaGetSymbolAddress((void**)&wr2, g_wr2);
    cudaGetSymbolAddress((void**)&wr3, g_wr3);

    // smem (bytes): B double buffer only
    const int SM1 = 2 * (2 * 100 * 12) * 4;   // 19200
    const int SM2 = 2 * (324 * 12) * 4;       // 31104
    const int SM3 = 2 * (18 * 34 * 12) * 4;   // 58752

    cudaFuncSetAttribute(convt3_h2,
                         cudaFuncAttributeMaxDynamicSharedMemorySize, SM3);

    leaf_kernel<<<BATCH, 32>>>(x, gw, gb, lp);
    mix_kernel<<<dim3(16, BATCH / 16), 256>>>(lp, z, bf0);
    prep_all<<<784, 256>>>(w1, wr1, w2, wr2, w3, wr3);

    // conv1: 128->128, 8x8 -> 16x16, ReLU. MGRP=4, IMGB=2, 3 blocks/SM
    convt_h2<128, 8, 128, 4, 2, true, 3>
        <<<dim3(4, BATCH / 2), 256, SM1>>>(bf0, wr1, b1, bf1);
    // conv2: 128->64, 16x16 -> 32x32, ReLU. MGRP=2, IMGB=1, 2 blocks/SM
    convt_h2<128, 16, 64, 2, 1, true, 2>
        <<<dim3(4, BATCH), 256, SM2>>>(bf1, wr2, b2, bf2);
    // conv3: 64->3, 32x32 -> 64x64
    convt3_h2<<<dim3(2, BATCH), 256, SM3>>>(bf2, wr3, b3, out);
}

// round 13
// speedup vs baseline: 1.3085x; 1.3085x over previous
#include <cuda_runtime.h>
#include <cuda_fp16.h>
#include <math.h>
#include <stdint.h>

#define BATCH 512
#define LATENT 128

// ---------------- scratch (static device arrays; no runtime allocs) ----------
__device__ float    g_lp[BATCH * 32];
// pixel-major half2 buffers: [n][pix][ch-words]
__device__ uint32_t g_b0[BATCH * 64 * 64];
__device__ uint32_t g_b1[BATCH * 256 * 64];
__device__ uint32_t g_b2[BATCH * 1024 * 32];
// per-lane A-fragment weights: conv1/2 [cls][c][tap][mt][lane][4w], conv3 [c][cls][tap][lane][2w]
__device__ uint32_t g_wr1[4 * 8 * 4 * 8 * 32 * 4];   // 131072
__device__ uint32_t g_wr2[4 * 8 * 4 * 4 * 32 * 4];   // 65536
__device__ uint32_t g_wr3[4 * 4 * 4 * 32 * 2];       // 4096

// ---------------- helpers ----------------
__device__ __forceinline__ uint32_t packh2(float lo, float hi) {
    __half2 h = __floats2half2_rn(lo, hi);
    return *(uint32_t*)&h;
}
__device__ __forceinline__ void mma_f16(float* d, const uint32_t* a, const uint32_t* b) {
    asm("mma.sync.aligned.m16n8k16.row.col.f32.f16.f16.f32 "
        "{%0,%1,%2,%3}, {%4,%5,%6,%7}, {%8,%9}, {%0,%1,%2,%3};"
        : "+f"(d[0]), "+f"(d[1]), "+f"(d[2]), "+f"(d[3])
        : "r"(a[0]), "r"(a[1]), "r"(a[2]), "r"(a[3]), "r"(b[0]), "r"(b[1]));
}
__device__ __forceinline__ void ldsm4(uint32_t* d, uint32_t addr) {
    asm volatile("ldmatrix.sync.aligned.m8n8.x4.shared.b16 {%0,%1,%2,%3}, [%4];"
                 : "=r"(d[0]), "=r"(d[1]), "=r"(d[2]), "=r"(d[3]) : "r"(addr));
}
__device__ __forceinline__ uint32_t smaddr(const void* p) {
    return (uint32_t)__cvta_generic_to_shared(p);
}
__device__ __forceinline__ void cp16(uint32_t* dst, const void* src) {
    uint32_t s = smaddr(dst);
    asm volatile("cp.async.ca.shared.global [%0], [%1], 16;" :: "r"(s), "l"(src) : "memory");
}
__device__ __forceinline__ void cp_commit() {
    asm volatile("cp.async.commit_group;" ::: "memory");
}
template <int N>
__device__ __forceinline__ void cp_wait() {
    asm volatile("cp.async.wait_group %0;" :: "n"(N) : "memory");
}

// ---------------- stage 1: gating + soft-tree leaf probabilities -------------
__global__ void leaf_kernel(const float* __restrict__ x,
                            const float* __restrict__ gw,
                            const float* __restrict__ gb,
                            float* __restrict__ lp) {
    int b = blockIdx.x;
    int lane = threadIdx.x;
    __shared__ float xs[LATENT];
    __shared__ float gs[32];
    for (int k = lane; k < LATENT; k += 32) xs[k] = x[b * LATENT + k];
    __syncthreads();
    if (lane < 31) {
        float acc = gb[lane];
#pragma unroll 8
        for (int k = 0; k < LATENT; k++) acc += xs[k] * gw[k * 31 + lane];
        gs[lane] = 1.0f / (1.0f + expf(-acc));
    }
    __syncthreads();
    float dens = 1.0f;
    int l = lane;
#pragma unroll
    for (int d = 1; d <= 5; d++) {
        int par  = l >> (6 - d);
        int gate = (1 << (d - 1)) - 1 + par;
        int bit  = (l >> (5 - d)) & 1;
        float gv = gs[gate];
        dens *= bit ? (1.0f - gv) : gv;
    }
    lp[b * 32 + l] = dens;
}

// ---------------- stage 2: mix, 16-batch tile, pixel-major half2 words -------
__global__ void mix_kernel(const float* __restrict__ lp,
                           const float* __restrict__ z,
                           uint32_t* __restrict__ out0) {
    __shared__ float lps[16][32];
    int tid = threadIdx.x;
    int idx = blockIdx.x * 256 + tid;
    int b0 = blockIdx.y * 16;
    for (int i = tid; i < 512; i += 256)
        lps[i >> 5][i & 31] = lp[b0 * 32 + i];
    __syncthreads();
    int icp = idx & 63, pix = idx >> 6;
    const float4* z0 = (const float4*)(z + (size_t)(2 * icp * 64 + pix) * 32);
    const float4* z1 = (const float4*)(z + (size_t)((2 * icp + 1) * 64 + pix) * 32);
    float4 zr0[8], zr1[8];
#pragma unroll
    for (int j = 0; j < 8; j++) { zr0[j] = z0[j]; zr1[j] = z1[j]; }
#pragma unroll
    for (int bb = 0; bb < 16; bb++) {
        const float* lr = lps[bb];
        float a0 = 0.0f, a1 = 0.0f;
#pragma unroll
        for (int j = 0; j < 8; j++) {
            float4 u = zr0[j], v = zr1[j];
            a0 += u.x * lr[4 * j] + u.y * lr[4 * j + 1] + u.z * lr[4 * j + 2] + u.w * lr[4 * j + 3];
            a1 += v.x * lr[4 * j] + v.y * lr[4 * j + 1] + v.z * lr[4 * j + 2] + v.w * lr[4 * j + 3];
        }
        out0[(size_t)(b0 + bb) * 4096 + pix * 64 + icp] = packh2(a0, a1);
    }
}

// ---------------- merged weight prep: per-lane mma A-fragments ---------------
template <int COUT, int MSHIFT>
__device__ __forceinline__ void prep_frag(const float* __restrict__ w,
                                          uint32_t* __restrict__ wr, int idx) {
    constexpr int MT = 1 << MSHIFT;
    if (idx >= 4 * 8 * 4 * MT * 32 * 4) return;
    int j    = idx & 3;
    int lane = (idx >> 2) & 31;
    int mt   = (idx >> 7) & (MT - 1);
    int t    = (idx >> (7 + MSHIFT)) & 3;
    int c    = (idx >> (9 + MSHIFT)) & 7;
    int cls  = idx >> (12 + MSHIFT);
    int lg = lane >> 2, lt = lane & 3;
    int m  = mt * 16 + lg + 8 * (j & 1);
    int kk = lt + 4 * (j >> 1);
    int py = cls >> 1, px = cls & 1;
    int ra = t >> 1, rb = t & 1;
    int ky = 3 - py - 2 * ra;
    int kx = 3 - px - 2 * rb;
    int ch = 2 * (c * 8 + kk);
    float v0 = w[((size_t)ch * COUT + m) * 16 + ky * 4 + kx];
    float v1 = w[((size_t)(ch + 1) * COUT + m) * 16 + ky * 4 + kx];
    wr[idx] = packh2(v0, v1);
}

__global__ void prep_all(const float* __restrict__ w1, uint32_t* __restrict__ wr1,
                         const float* __restrict__ w2, uint32_t* __restrict__ wr2,
                         const float* __restrict__ w3, uint32_t* __restrict__ wr3) {
    int g = blockIdx.x;
    int tid = threadIdx.x;
    if (g < 512)      prep_frag<128, 3>(w1, wr1, g * 256 + tid);
    else if (g < 768) prep_frag<64, 2>(w2, wr2, (g - 512) * 256 + tid);
    else {
        int idx = (g - 768) * 256 + tid;
        if (idx >= 4096) return;
        int j    = idx & 1;
        int lane = (idx >> 1) & 31;
        int t    = (idx >> 6) & 3;
        int cls  = (idx >> 8) & 3;
        int c    = idx >> 10;
        int lg = lane >> 2, lt = lane & 3;
        int kk = lt + 4 * j;
        int oc = lg;
        int py = cls >> 1, px = cls & 1;
        int ra = t >> 1, rb = t & 1;
        int ky = 3 - py - 2 * ra;
        int kx = 3 - px - 2 * rb;
        int ch = 2 * (c * 8 + kk);
        float v0 = 0.0f, v1 = 0.0f;
        if (oc < 3) {
            v0 = w3[((size_t)ch * 3 + oc) * 16 + ky * 4 + kx];
            v1 = w3[((size_t)(ch + 1) * 3 + oc) * 16 + ky * 4 + kx];
        }
        wr3[idx] = packh2(v0, v1);
    }
}

// ---------------- conv1/conv2: fp16 mma, per-tap pipelined A LDG -------------
// NBLK=2 is load-bearing: 128-reg budget. NBLK=3 (80 regs) spills accumulators
// to local memory (round 12: DRAM 32%, 2.4x slower). Do not raise.
template <int CIN, int HIN, int COUT, int MGRP, int IMGB, bool RELU>
__launch_bounds__(256, 2)
__global__ void convt_h2(const uint32_t* __restrict__ in,
                         const uint32_t* __restrict__ wr,
                         const float* __restrict__ bias,
                         uint32_t* __restrict__ out) {
    constexpr int NPIX = HIN * HIN;
    constexpr int HOUT = 2 * HIN;
    constexpr int PW   = HIN + 2;
    constexpr int PPIX = PW * PW;
    constexpr int NGRP = 8 / MGRP;
    constexpr int NSUB = IMGB * NPIX / (8 * NGRP);
    constexpr int LOGH = (HIN == 8) ? 3 : 4;
    constexpr int MT   = COUT / 16;
    constexpr int ICPW = CIN / 2;
    constexpr int OCPW = COUT / 2;
    constexpr int NCH  = CIN / 16;
    constexpr int BSZ  = IMGB * PPIX * 12;

    extern __shared__ uint32_t smu[];
    uint32_t* Bbuf[2] = { smu, smu + BSZ };

    const int cls = blockIdx.x;
    const int img0 = blockIdx.y * IMGB;
    const int py = cls >> 1, px = cls & 1;
    const int tid = threadIdx.x;
    const int warp = tid >> 5, lane = tid & 31;
    const int lg = lane >> 2, lt = lane & 3;
    const int m0 = (warp % MGRP) * 32;
    const int n0 = (warp / MGRP) * (NSUB * 8);

    for (int i = tid; i < 2 * BSZ; i += 256) Bbuf[0][i] = 0;
    __syncthreads();

    int toffB[4];
#pragma unroll
    for (int t = 0; t < 4; t++)
        toffB[t] = ((py - 1 + (t >> 1)) * PW + (px - 1 + (t & 1))) * 48;

    uint32_t bslot[NSUB / 2];
#pragma unroll
    for (int j = 0; j < NSUB / 2; j++) {
        int s = 2 * j + (lane >> 4);
        int n = n0 + s * 8 + (lane & 7);
        int im = n >> (2 * LOGH);
        int pix = n & (NPIX - 1);
        int q = pix >> LOGH, r = pix & (HIN - 1);
        bslot[j] = (im * PPIX + (q + 1) * PW + (r + 1)) * 48 + ((lane >> 3) & 1) * 16;
    }

    float d[2][NSUB][4];
#pragma unroll
    for (int mm = 0; mm < 2; mm++)
#pragma unroll
        for (int s = 0; s < NSUB; s++)
#pragma unroll
            for (int j = 0; j < 4; j++) d[mm][s][j] = 0.0f;

    // A fragment base: [cls][c][tap][mt][lane][4]
    const uint32_t* wA = wr + ((size_t)cls * NCH * 4 * MT + (m0 >> 4)) * 128 + lane * 4;

    auto prefetchB = [&](int c) {
        uint32_t* B = Bbuf[c & 1];
        for (int idx = tid; idx < IMGB * NPIX * 2; idx += 256) {
            int part = idx & 1;
            int rest = idx >> 1;
            int pix = rest & (NPIX - 1);
            int im  = rest >> (2 * LOGH);
            int q = pix >> LOGH, r = pix & (HIN - 1);
            cp16(B + (im * PPIX + (q + 1) * PW + (r + 1)) * 12 + part * 4,
                 in + ((size_t)(img0 + im) * NPIX + pix) * ICPW + c * 8 + part * 4);
        }
    };

    prefetchB(0);
    cp_commit();

    for (int c = 0; c < NCH; c++) {
        const uint32_t* wAc = wA + (size_t)(c * 4) * MT * 128;
        // tap-0 A fragments issue before the wait (overlaps staging latency)
        uint4 a_cur[2], a_nxt[2];
        a_cur[0] = *(const uint4*)(wAc);
        a_cur[1] = *(const uint4*)(wAc + 128);

        if (c + 1 < NCH) { prefetchB(c + 1); cp_commit(); cp_wait<1>(); }
        else             { cp_wait<0>(); }
        __syncthreads();
        const uint32_t bb = smaddr(Bbuf[c & 1]);

#pragma unroll
        for (int t = 0; t < 4; t++) {
            if (t < 3) {
                const uint32_t* wAn = wAc + (size_t)(t + 1) * MT * 128;
                a_nxt[0] = *(const uint4*)(wAn);
                a_nxt[1] = *(const uint4*)(wAn + 128);
            }
            const int tb = toffB[t];
#pragma unroll
            for (int j = 0; j < NSUB / 2; j++) {
                uint32_t bf[4];
                ldsm4(bf, bb + bslot[j] + tb);
                mma_f16(d[0][2 * j],     (const uint32_t*)&a_cur[0], bf + 0);
                mma_f16(d[1][2 * j],     (const uint32_t*)&a_cur[1], bf + 0);
                mma_f16(d[0][2 * j + 1], (const uint32_t*)&a_cur[0], bf + 2);
                mma_f16(d[1][2 * j + 1], (const uint32_t*)&a_cur[1], bf + 2);
            }
            if (t < 3) { a_cur[0] = a_nxt[0]; a_cur[1] = a_nxt[1]; }
        }
        __syncthreads();
    }

    // epilogue: bias(+ReLU), shfl pair-exchange, pixel-major packed writes
    float bv[2][2];
#pragma unroll
    for (int mm = 0; mm < 2; mm++) {
        bv[mm][0] = bias[m0 + mm * 16 + lg];
        bv[mm][1] = bias[m0 + mm * 16 + lg + 8];
    }
#pragma unroll
    for (int mm = 0; mm < 2; mm++) {
#pragma unroll
        for (int s = 0; s < NSUB; s++) {
            int nb = n0 + s * 8 + 2 * lt;
            int im = nb >> (2 * LOGH);
            int pix = nb & (NPIX - 1);
            int q = pix >> LOGH, r = pix & (HIN - 1);
            int op0 = (2 * q + py) * HOUT + 2 * r + px;
            uint32_t* outw = out + (size_t)(img0 + im) * HOUT * HOUT * OCPW;
#pragma unroll
            for (int half = 0; half < 2; half++) {
                int oc = m0 + mm * 16 + lg + 8 * half;
                float v0 = d[mm][s][2 * half]     + bv[mm][half];
                float v1 = d[mm][s][2 * half + 1] + bv[mm][half];
                if (RELU) { v0 = fmaxf(v0, 0.0f); v1 = fmaxf(v1, 0.0f); }
                float p0 = __shfl_down_sync(0xffffffffu, v0, 4);
                float p1 = __shfl_down_sync(0xffffffffu, v1, 4);
                if (!(lg & 1)) {
                    int ocp = oc >> 1;
                    outw[(size_t)op0 * OCPW + ocp]       = packh2(v0, p0);
                    outw[(size_t)(op0 + 2) * OCPW + ocp] = packh2(v1, p1);
                }
            }
        }
    }
}

// ---------------- conv3: fused classes, swapped roles, weights by LDG --------
__launch_bounds__(256, 2)
__global__ void convt3_h2(const uint32_t* __restrict__ in,
                          const uint32_t* __restrict__ wr,
                          const float* __restrict__ bias,
                          float* __restrict__ out) {
    constexpr int HIN = 32, HOUT = 64;
    constexpr int PW = HIN + 2;
    constexpr int ROWS = 18;
    constexpr int PSUB = 4;
    constexpr int BSZ = ROWS * PW * 12;

    extern __shared__ uint32_t smu[];
    uint32_t* Bbuf[2] = { smu, smu + BSZ };

    const int q0 = blockIdx.x * 16;
    const int img = blockIdx.y;
    const int tid = threadIdx.x;
    const int warp = tid >> 5, lane = tid & 31;
    const int lg = lane >> 2, lt = lane & 3;

    for (int i = tid; i < 2 * BSZ; i += 256) Bbuf[0][i] = 0;
    __syncthreads();

    uint32_t aslot[PSUB];
#pragma unroll
    for (int s = 0; s < PSUB; s++) {
        int p = warp * 64 + s * 16;
        int ql = p >> 5, r0 = p & 31;
        aslot[s] = ((ql + 1) * PW + r0 + 1 + (lane & 7) + 8 * ((lane >> 3) & 1)) * 48
                 + (lane >> 4) * 16;
    }

    float d[4][PSUB][4];
#pragma unroll
    for (int c = 0; c < 4; c++)
#pragma unroll
        for (int s = 0; s < PSUB; s++)
#pragma unroll
            for (int j = 0; j < 4; j++) d[c][s][j] = 0.0f;

    auto prefetchB = [&](int c) {
        uint32_t* B = Bbuf[c & 1];
        for (int idx = tid; idx < ROWS * 32 * 2; idx += 256) {
            int part = idx & 1;
            int rest = idx >> 1;
            int col = rest & 31;
            int rr  = rest >> 5;
            int row = q0 - 1 + rr;
            if (row >= 0 && row < HIN)
                cp16(B + (rr * PW + col + 1) * 12 + part * 4,
                     in + ((size_t)img * 1024 + row * 32 + col) * 32 + c * 8 + part * 4);
        }
    };

    prefetchB(0);
    cp_commit();

    for (int c = 0; c < 4; c++) {
        if (c + 1 < 4) { prefetchB(c + 1); cp_commit(); cp_wait<1>(); }
        else           { cp_wait<0>(); }
        __syncthreads();
        const uint32_t bb = smaddr(Bbuf[c & 1]);

#pragma unroll
        for (int cls = 0; cls < 4; cls++) {
            const int py = cls >> 1, px = cls & 1;
            uint2 wv[4];
#pragma unroll
            for (int t = 0; t < 4; t++)
                wv[t] = *(const uint2*)(wr + (((c * 4 + cls) * 4 + t) * 32 + lane) * 2);
#pragma unroll
            for (int t = 0; t < 4; t++) {
                const int ra = t >> 1, rb = t & 1;
                const int sh = ((py - 1 + ra) * PW + (px - 1 + rb)) * 48;
                uint32_t b[2] = { wv[t].x, wv[t].y };
#pragma unroll
                for (int s = 0; s < PSUB; s++) {
                    uint32_t af[4];
                    ldsm4(af, bb + aslot[s] + sh);
                    mma_f16(d[cls][s], af, b);
                }
            }
        }
        __syncthreads();
    }

    float bias_s[3];
    bias_s[0] = bias[0]; bias_s[1] = bias[1]; bias_s[2] = bias[2];
    float* outb = out + (size_t)img * 3 * HOUT * HOUT;
    if (lt < 2) {
#pragma unroll
        for (int cls = 0; cls < 4; cls++) {
            const int py = cls >> 1, px = cls & 1;
#pragma unroll
            for (int s = 0; s < PSUB; s++) {
#pragma unroll
                for (int rowh = 0; rowh < 2; rowh++) {
                    int p = warp * 64 + s * 16 + lg + 8 * rowh;
                    int q = q0 + (p >> 5), r = p & 31;
                    int oy = 2 * q + py, ox = 2 * r + px;
#pragma unroll
                    for (int cc = 0; cc < 2; cc++) {
                        int oc = 2 * lt + cc;
                        if (oc < 3) {
                            float v = d[cls][s][2 * rowh + cc] + bias_s[oc];
                            outb[((size_t)oc * HOUT + oy) * HOUT + ox] = v;
                        }
                    }
                }
            }
        }
    }
}

// ---------------- launch -----------------------------------------------------
extern "C" void kernel_launch(void* const* d_in, const int* in_sizes, int n_in,
                              void* d_out, int out_size) {
    const float* x  = (const float*)d_in[0];
    const float* gw = (const float*)d_in[1];
    const float* gb = (const float*)d_in[2];
    const float* z  = (const float*)d_in[3];
    const float* w1 = (const float*)d_in[4];
    const float* b1 = (const float*)d_in[5];
    const float* w2 = (const float*)d_in[6];
    const float* b2 = (const float*)d_in[7];
    const float* w3 = (const float*)d_in[8];
    const float* b3 = (const float*)d_in[9];
    float* out = (float*)d_out;

    float *lp;
    uint32_t *bf0, *bf1, *bf2, *wr1, *wr2, *wr3;
    cudaGetSymbolAddress((void**)&lp,  g_lp);
    cudaGetSymbolAddress((void**)&bf0, g_b0);
    cudaGetSymbolAddress((void**)&bf1, g_b1);
    cudaGetSymbolAddress((void**)&bf2, g_b2);
    cudaGetSymbolAddress((void**)&wr1, g_wr1);
    cudaGetSymbolAddress((void**)&wr2, g_wr2);
    cudaGetSymbolAddress((void**)&wr3, g_wr3);

    // smem (bytes): B double buffer only
    const int SM1 = 2 * (2 * 100 * 12) * 4;   // 19200
    const int SM2 = 2 * (324 * 12) * 4;       // 31104
    const int SM3 = 2 * (18 * 34 * 12) * 4;   // 58752

    cudaFuncSetAttribute(convt3_h2,
                         cudaFuncAttributeMaxDynamicSharedMemorySize, SM3);

    leaf_kernel<<<BATCH, 32>>>(x, gw, gb, lp);
    mix_kernel<<<dim3(16, BATCH / 16), 256>>>(lp, z, bf0);
    prep_all<<<784, 256>>>(w1, wr1, w2, wr2, w3, wr3);

    // conv1: 128->128, 8x8 -> 16x16, ReLU. MGRP=4, IMGB=2, 2 blocks/SM
    convt_h2<128, 8, 128, 4, 2, true>
        <<<dim3(4, BATCH / 2), 256, SM1>>>(bf0, wr1, b1, bf1);
    // conv2: 128->64, 16x16 -> 32x32, ReLU. MGRP=2, IMGB=1, 2 blocks/SM
    convt_h2<128, 16, 64, 2, 1, true>
        <<<dim3(4, BATCH), 256, SM2>>>(bf1, wr2, b2, bf2);
    // conv3: 64->3, 32x32 -> 64x64
    convt3_h2<<<dim3(2, BATCH), 256, SM3>>>(bf2, wr3, b3, out);
}